// round 9
// baseline (speedup 1.0000x reference)
#include <cuda_runtime.h>

// 4-D average pool, kernel=stride=2, padding=0.
// Input : [2, 16, 32, 32, 32, 32] fp32  (33,554,432 elems, 128 MiB)
// Output: [2, 16, 16, 16, 16, 16] fp32  ( 2,097,152 elems,   8 MiB)
//
// Pure streaming: each input element read exactly once -> HBM-bound.
// Each thread produces FOUR adjacent outputs along the last dim (one
// float4 store). Per corner of the 2x2x2 (d1,d2,d3) window it reads
// 8 consecutive floats = 2 aligned float4s: 16 independent 128-bit
// streaming loads, front-batched. 32-bit indexing. The grid exactly
// covers n_quads (524288 = 2048 * 256) so the hot kernel has no
// bounds guard; a guarded fallback handles any other shape.

#define IN_D   32           // input extent of each pooled dim
#define OUT_D  16           // output extent of each pooled dim
#define QUADS_PER_ROW 4     // OUT_D / 4 output-quads along last dim

template <bool GUARD>
__global__ __launch_bounds__(256)
void avgpool4d_k2s2_kernel(const float4* __restrict__ in4,
                           float4* __restrict__ out4,
                           unsigned n_quads)
{
    unsigned q = blockIdx.x * blockDim.x + threadIdx.x;
    if (GUARD && q >= n_quads) return;

    // Decompose quad index q over output [BC, 16, 16, 16, 4 quads]
    unsigned q4 = q & (QUADS_PER_ROW - 1);       // quad index along d4
    unsigned r  = q >> 2;
    unsigned d3 = r & (OUT_D - 1);  r >>= 4;
    unsigned d2 = r & (OUT_D - 1);  r >>= 4;
    unsigned d1 = r & (OUT_D - 1);  r >>= 4;
    unsigned bc = r;                             // 0..31 (B*C)

    // Base index in float4 units (input strides are all multiples of 4 floats):
    // floats: bc:32^4=1048576, i1:32^3=32768, i2:32^2=1024, i3:32, i4:1
    // float4: bc:262144,       i1:8192,       i2:256,       i3:8,  q4 step:2
    unsigned base = bc * 262144u + d1 * 16384u + d2 * 512u + d3 * 16u + q4 * 2u;

    const unsigned S1 = 8192u;   // +1 in i1 (float4 units)
    const unsigned S2 = 256u;    // +1 in i2
    const unsigned S3 = 8u;      // +1 in i3

    // 8 corners x 2 float4s each = 16 independent 128-bit streaming loads.
    float4 a0 = __ldcs(in4 + base);
    float4 b0 = __ldcs(in4 + base + 1);
    float4 a1 = __ldcs(in4 + base + S3);
    float4 b1 = __ldcs(in4 + base + S3 + 1);
    float4 a2 = __ldcs(in4 + base + S2);
    float4 b2 = __ldcs(in4 + base + S2 + 1);
    float4 a3 = __ldcs(in4 + base + S2 + S3);
    float4 b3 = __ldcs(in4 + base + S2 + S3 + 1);
    float4 a4 = __ldcs(in4 + base + S1);
    float4 b4 = __ldcs(in4 + base + S1 + 1);
    float4 a5 = __ldcs(in4 + base + S1 + S3);
    float4 b5 = __ldcs(in4 + base + S1 + S3 + 1);
    float4 a6 = __ldcs(in4 + base + S1 + S2);
    float4 b6 = __ldcs(in4 + base + S1 + S2 + 1);
    float4 a7 = __ldcs(in4 + base + S1 + S2 + S3);
    float4 b7 = __ldcs(in4 + base + S1 + S2 + S3 + 1);

    // Output element j (j=0..3) sums input i4 = {2j, 2j+1} across 8 corners.
    // a* covers i4 0..3 (outputs 0,1), b* covers i4 4..7 (outputs 2,3).
    float o0 = (a0.x + a0.y) + (a1.x + a1.y) + (a2.x + a2.y) + (a3.x + a3.y)
             + (a4.x + a4.y) + (a5.x + a5.y) + (a6.x + a6.y) + (a7.x + a7.y);
    float o1 = (a0.z + a0.w) + (a1.z + a1.w) + (a2.z + a2.w) + (a3.z + a3.w)
             + (a4.z + a4.w) + (a5.z + a5.w) + (a6.z + a6.w) + (a7.z + a7.w);
    float o2 = (b0.x + b0.y) + (b1.x + b1.y) + (b2.x + b2.y) + (b3.x + b3.y)
             + (b4.x + b4.y) + (b5.x + b5.y) + (b6.x + b6.y) + (b7.x + b7.y);
    float o3 = (b0.z + b0.w) + (b1.z + b1.w) + (b2.z + b2.w) + (b3.z + b3.w)
             + (b4.z + b4.w) + (b5.z + b5.w) + (b6.z + b6.w) + (b7.z + b7.w);

    const float inv16 = 0.0625f;   // 1/2^4
    __stcs(out4 + q, make_float4(o0 * inv16, o1 * inv16, o2 * inv16, o3 * inv16));
}

extern "C" void kernel_launch(void* const* d_in, const int* in_sizes, int n_in,
                              void* d_out, int out_size)
{
    const float4* in4 = (const float4*)d_in[0];
    float4* out4 = (float4*)d_out;

    unsigned n_quads = (unsigned)(out_size / 4);         // 524,288
    const unsigned threads = 256;

    if (n_quads % threads == 0) {
        // Exact grid: no bounds guard in the hot kernel.
        avgpool4d_k2s2_kernel<false><<<n_quads / threads, threads>>>(in4, out4, n_quads);
    } else {
        unsigned blocks = (n_quads + threads - 1) / threads;
        avgpool4d_k2s2_kernel<true><<<blocks, threads>>>(in4, out4, n_quads);
    }
}

// round 13
// speedup vs baseline: 1.0544x; 1.0544x over previous
#include <cuda_runtime.h>

// 4-D average pool, kernel=stride=2, padding=0.
// Input : [2, 16, 32, 32, 32, 32] fp32  (33,554,432 elems, 128 MiB)
// Output: [2, 16, 16, 16, 16, 16] fp32  ( 2,097,152 elems,   8 MiB)
//
// R9 ncu: DRAM=70.9% with regs=32 -> ptxas serialized the load chain
// (32 regs can't hold 16 live float4s). This version forces high MLP:
//   - __launch_bounds__(256, 3): up to 85 regs/thread, room for all
//     16 loads to be in flight simultaneously.
//   - loads go into a 16-element array, reduction strictly afterward,
//     so no accumulator reuse can serialize the batch.

#define IN_D   32           // input extent of each pooled dim
#define OUT_D  16           // output extent of each pooled dim
#define QUADS_PER_ROW 4     // OUT_D / 4 output-quads along last dim

template <bool GUARD>
__global__ __launch_bounds__(256, 3)
void avgpool4d_k2s2_kernel(const float4* __restrict__ in4,
                           float4* __restrict__ out4,
                           unsigned n_quads)
{
    unsigned q = blockIdx.x * blockDim.x + threadIdx.x;
    if (GUARD && q >= n_quads) return;

    // Decompose quad index q over output [BC, 16, 16, 16, 4 quads]
    unsigned q4 = q & (QUADS_PER_ROW - 1);       // quad index along d4
    unsigned r  = q >> 2;
    unsigned d3 = r & (OUT_D - 1);  r >>= 4;
    unsigned d2 = r & (OUT_D - 1);  r >>= 4;
    unsigned d1 = r & (OUT_D - 1);  r >>= 4;
    unsigned bc = r;                             // 0..31 (B*C)

    // Base index in float4 units:
    // float4 strides: bc:262144, i1:8192, i2:256, i3:8, q4 step:2
    unsigned base = bc * 262144u + d1 * 16384u + d2 * 512u + d3 * 16u + q4 * 2u;

    const unsigned S1 = 8192u;   // +1 in i1 (float4 units)
    const unsigned S2 = 256u;    // +1 in i2
    const unsigned S3 = 8u;      // +1 in i3

    // Offsets of the 8 corners of the 2x2x2 (d1,d2,d3) window.
    const unsigned off[8] = {
        0u,        S3,        S2,        S2 + S3,
        S1,        S1 + S3,   S1 + S2,   S1 + S2 + S3
    };

    // Phase 1: issue ALL 16 independent 128-bit streaming loads.
    float4 v[16];
#pragma unroll
    for (int c = 0; c < 8; ++c) {
        v[2*c]     = __ldcs(in4 + base + off[c]);
        v[2*c + 1] = __ldcs(in4 + base + off[c] + 1);
    }

    // Phase 2: reduce. Output j (0..3) sums i4 = {2j, 2j+1} over 8 corners.
    // Even v[] cover i4 0..3 (outputs 0,1); odd v[] cover i4 4..7 (outputs 2,3).
    float o0 = 0.f, o1 = 0.f, o2 = 0.f, o3 = 0.f;
#pragma unroll
    for (int c = 0; c < 8; ++c) {
        o0 += v[2*c].x + v[2*c].y;
        o1 += v[2*c].z + v[2*c].w;
        o2 += v[2*c + 1].x + v[2*c + 1].y;
        o3 += v[2*c + 1].z + v[2*c + 1].w;
    }

    const float inv16 = 0.0625f;   // 1/2^4
    __stcs(out4 + q, make_float4(o0 * inv16, o1 * inv16, o2 * inv16, o3 * inv16));
}

extern "C" void kernel_launch(void* const* d_in, const int* in_sizes, int n_in,
                              void* d_out, int out_size)
{
    const float4* in4 = (const float4*)d_in[0];
    float4* out4 = (float4*)d_out;

    unsigned n_quads = (unsigned)(out_size / 4);         // 524,288
    const unsigned threads = 256;

    if (n_quads % threads == 0) {
        // Exact grid: no bounds guard in the hot kernel.
        avgpool4d_k2s2_kernel<false><<<n_quads / threads, threads>>>(in4, out4, n_quads);
    } else {
        unsigned blocks = (n_quads + threads - 1) / threads;
        avgpool4d_k2s2_kernel<true><<<blocks, threads>>>(in4, out4, n_quads);
    }
}

// round 14
// speedup vs baseline: 1.0651x; 1.0102x over previous
#include <cuda_runtime.h>

// 4-D average pool, kernel=stride=2, padding=0.
// Input : [2, 16, 32, 32, 32, 32] fp32  (33,554,432 elems, 128 MiB)
// Output: [2, 16, 16, 16, 16, 16] fp32  ( 2,097,152 elems,   8 MiB)
//
// R13 ncu: regs=70, DRAM=76.5%, occ=32.4% (3 CTA/SM). Latency-hiding is
// fixed (42KB in flight/SM >> 24KB needed); residual loss is wave
// quantization: 2048 CTAs / (3*152 concurrent) = 4.6 waves, each
// transition paying T_wave_trans + a fresh-CTA load-latency bubble.
// Fix: persistent grid of exactly 3*numSMs CTAs, grid-stride loop.
// Body unchanged: 16 front-batched 128-bit streaming loads into an
// array, reduce strictly afterward (keeps effective MLP=16).

#define OUT_D  16           // output extent of each pooled dim
#define QUADS_PER_ROW 4     // OUT_D / 4 output-quads along last dim

__global__ __launch_bounds__(256, 3)
void avgpool4d_k2s2_kernel(const float4* __restrict__ in4,
                           float4* __restrict__ out4,
                           unsigned n_quads)
{
    const unsigned stride = gridDim.x * blockDim.x;

    for (unsigned q = blockIdx.x * blockDim.x + threadIdx.x;
         q < n_quads; q += stride)
    {
        // Decompose quad index q over output [BC, 16, 16, 16, 4 quads]
        unsigned q4 = q & (QUADS_PER_ROW - 1);       // quad index along d4
        unsigned r  = q >> 2;
        unsigned d3 = r & (OUT_D - 1);  r >>= 4;
        unsigned d2 = r & (OUT_D - 1);  r >>= 4;
        unsigned d1 = r & (OUT_D - 1);  r >>= 4;
        unsigned bc = r;                             // 0..31 (B*C)

        // Base index in float4 units:
        // float4 strides: bc:262144, i1:8192, i2:256, i3:8, q4 step:2
        unsigned base = bc * 262144u + d1 * 16384u + d2 * 512u + d3 * 16u + q4 * 2u;

        const unsigned S1 = 8192u;   // +1 in i1 (float4 units)
        const unsigned S2 = 256u;    // +1 in i2
        const unsigned S3 = 8u;      // +1 in i3

        // Offsets of the 8 corners of the 2x2x2 (d1,d2,d3) window.
        const unsigned off[8] = {
            0u,        S3,        S2,        S2 + S3,
            S1,        S1 + S3,   S1 + S2,   S1 + S2 + S3
        };

        // Phase 1: issue ALL 16 independent 128-bit streaming loads.
        float4 v[16];
#pragma unroll
        for (int c = 0; c < 8; ++c) {
            v[2*c]     = __ldcs(in4 + base + off[c]);
            v[2*c + 1] = __ldcs(in4 + base + off[c] + 1);
        }

        // Phase 2: reduce. Output j (0..3) sums i4={2j,2j+1} over 8 corners.
        float o0 = 0.f, o1 = 0.f, o2 = 0.f, o3 = 0.f;
#pragma unroll
        for (int c = 0; c < 8; ++c) {
            o0 += v[2*c].x + v[2*c].y;
            o1 += v[2*c].z + v[2*c].w;
            o2 += v[2*c + 1].x + v[2*c + 1].y;
            o3 += v[2*c + 1].z + v[2*c + 1].w;
        }

        const float inv16 = 0.0625f;   // 1/2^4
        __stcs(out4 + q, make_float4(o0 * inv16, o1 * inv16,
                                     o2 * inv16, o3 * inv16));
    }
}

extern "C" void kernel_launch(void* const* d_in, const int* in_sizes, int n_in,
                              void* d_out, int out_size)
{
    const float4* in4 = (const float4*)d_in[0];
    float4* out4 = (float4*)d_out;

    unsigned n_quads = (unsigned)(out_size / 4);         // 524,288

    // Persistent grid: exactly 3 CTAs per SM (matches launch_bounds),
    // single wave, no CTA-switch bubbles. Host code runs only at graph
    // capture; replays use the captured grid.
    int num_sms = 0;
    cudaDeviceGetAttribute(&num_sms, cudaDevAttrMultiProcessorCount, 0);
    if (num_sms <= 0) num_sms = 148;                     // defensive fallback
    unsigned blocks = (unsigned)(3 * num_sms);           // 456 on GB300
    // Never launch more blocks than there are quads (tiny-shape safety).
    unsigned max_blocks = (n_quads + 255u) / 256u;
    if (blocks > max_blocks) blocks = max_blocks;

    avgpool4d_k2s2_kernel<<<blocks, 256>>>(in4, out4, n_quads);
}